// round 4
// baseline (speedup 1.0000x reference)
#include <cuda_runtime.h>

// Problem constants: B=4, S=2048, D=1024, U=1024, fp32 throughout.
#define BB 4
#define SSQ 2048
#define DD 1024
#define UU 1024

// Scratch (device globals: allocation-free, per harness rules).
// Q,K,V: 3 x 32MB; scores/probs: 64MB.
__device__ float g_q[(size_t)BB * SSQ * UU];
__device__ float g_k[(size_t)BB * SSQ * UU];
__device__ float g_v[(size_t)BB * SSQ * UU];
__device__ float g_s[(size_t)BB * SSQ * SSQ];

// ---------------------------------------------------------------------------
// Packed fp32x2 helpers (Blackwell FFMA2 path: double-rate fp32 FMA).
// ---------------------------------------------------------------------------
__device__ __forceinline__ unsigned long long fma2(unsigned long long a,
                                                   unsigned long long b,
                                                   unsigned long long c) {
    unsigned long long d;
    asm("fma.rn.f32x2 %0, %1, %2, %3;" : "=l"(d) : "l"(a), "l"(b), "l"(c));
    return d;
}
__device__ __forceinline__ unsigned long long dup2(float x) {
    unsigned long long r;
    asm("mov.b64 %0, {%1, %1};" : "=l"(r) : "f"(x));
    return r;
}
__device__ __forceinline__ float2 unpack2(unsigned long long v) {
    float2 f;
    asm("mov.b64 {%0, %1}, %2;" : "=f"(f.x), "=f"(f.y) : "l"(v));
    return f;
}

// ---------------------------------------------------------------------------
// 128x128x16 tiled fp32 GEMM, 256 threads, 8x8 per-thread microtile computed
// as 8x4 fma.rn.f32x2. Register-prefetch pipeline (load next k-tile into regs
// while computing current one from smem).
//   C[M,N] = A[M,K] @ B            (TRANS_B=false: B is [K,N] row-major)
//   C[M,N] = A[M,K] @ B^T          (TRANS_B=true : B is [N,K] row-major)
// Requires M,N % 128 == 0 and K % 16 == 0 (holds for all shapes here).
// blockIdx.z selects a batch slice via the given strides.
// ---------------------------------------------------------------------------
template <bool TRANS_B>
__global__ __launch_bounds__(256, 2)
void gemm128x128(const float* __restrict__ Ag, const float* __restrict__ Bg,
                 float* __restrict__ Cg, int M, int N, int K,
                 long long sA, long long sB, long long sC)
{
    const float* A = Ag + (long long)blockIdx.z * sA;
    const float* B = Bg + (long long)blockIdx.z * sB;
    float*       C = Cg + (long long)blockIdx.z * sC;

    __shared__ float As[16][132];   // [k][m], padded; 128B-row-aligned for f4
    __shared__ float Bs[16][132];   // [k][n], padded

    const int tid = threadIdx.x;
    const int tx  = tid & 15;       // n-tile coord (8 cols each)
    const int ty  = tid >> 4;       // m-tile coord (8 rows each)
    const int m0  = blockIdx.y * 128;
    const int n0  = blockIdx.x * 128;

    // A staging: 128 rows x 16 k. Each thread: rows (ar, ar+64), 4 k's.
    const int ar  = tid >> 2;           // 0..63
    const int ac4 = (tid & 3) * 4;      // k offset within tile
    const float* Ap = A + (size_t)(m0 + ar) * K + ac4;

    // B staging.
    int br, bc4;
    const float* Bp;
    if (TRANS_B) {                       // B[N,K]: like A but over n rows
        br  = tid >> 2;  bc4 = (tid & 3) * 4;
        Bp  = B + (size_t)(n0 + br) * K + bc4;
    } else {                             // B[K,N]: rows (br, br+8), 4 n's
        br  = tid >> 5;  bc4 = (tid & 31) * 4;
        Bp  = B + (size_t)br * N + n0 + bc4;
    }

    unsigned long long acc[8][4];
    #pragma unroll
    for (int i = 0; i < 8; ++i)
        #pragma unroll
        for (int j = 0; j < 4; ++j) acc[i][j] = 0ull;

    const int iters = K / 16;

    // Prologue prefetch (tile 0) into registers.
    float4 ra0 = *(const float4*)(Ap);
    float4 ra1 = *(const float4*)(Ap + (size_t)64 * K);
    float4 rb0, rb1;
    if (TRANS_B) {
        rb0 = *(const float4*)(Bp);
        rb1 = *(const float4*)(Bp + (size_t)64 * K);
    } else {
        rb0 = *(const float4*)(Bp);
        rb1 = *(const float4*)(Bp + (size_t)8 * N);
    }

    for (int t = 0; t < iters; ++t) {
        // Commit staged registers to smem (A/NT-B transposed scatter).
        As[ac4 + 0][ar]      = ra0.x; As[ac4 + 1][ar]      = ra0.y;
        As[ac4 + 2][ar]      = ra0.z; As[ac4 + 3][ar]      = ra0.w;
        As[ac4 + 0][ar + 64] = ra1.x; As[ac4 + 1][ar + 64] = ra1.y;
        As[ac4 + 2][ar + 64] = ra1.z; As[ac4 + 3][ar + 64] = ra1.w;
        if (TRANS_B) {
            Bs[bc4 + 0][br]      = rb0.x; Bs[bc4 + 1][br]      = rb0.y;
            Bs[bc4 + 2][br]      = rb0.z; Bs[bc4 + 3][br]      = rb0.w;
            Bs[bc4 + 0][br + 64] = rb1.x; Bs[bc4 + 1][br + 64] = rb1.y;
            Bs[bc4 + 2][br + 64] = rb1.z; Bs[bc4 + 3][br + 64] = rb1.w;
        } else {
            *(float4*)&Bs[br][bc4]     = rb0;
            *(float4*)&Bs[br + 8][bc4] = rb1;
        }
        __syncthreads();

        // Prefetch next tile (overlaps with compute below).
        if (t + 1 < iters) {
            Ap += 16;
            ra0 = *(const float4*)(Ap);
            ra1 = *(const float4*)(Ap + (size_t)64 * K);
            if (TRANS_B) {
                Bp += 16;
                rb0 = *(const float4*)(Bp);
                rb1 = *(const float4*)(Bp + (size_t)64 * K);
            } else {
                Bp += (size_t)16 * N;
                rb0 = *(const float4*)(Bp);
                rb1 = *(const float4*)(Bp + (size_t)8 * N);
            }
        }

        // Compute: 16 k-steps, 8x8 per thread via packed f32x2 FMA.
        #pragma unroll
        for (int kk = 0; kk < 16; ++kk) {
            float4 a0 = *(const float4*)&As[kk][ty * 8];
            float4 a1 = *(const float4*)&As[kk][ty * 8 + 4];
            const unsigned long long* bp =
                (const unsigned long long*)&Bs[kk][tx * 8];
            unsigned long long b0 = bp[0], b1 = bp[1], b2 = bp[2], b3 = bp[3];
            unsigned long long a2[8];
            a2[0] = dup2(a0.x); a2[1] = dup2(a0.y);
            a2[2] = dup2(a0.z); a2[3] = dup2(a0.w);
            a2[4] = dup2(a1.x); a2[5] = dup2(a1.y);
            a2[6] = dup2(a1.z); a2[7] = dup2(a1.w);
            #pragma unroll
            for (int i = 0; i < 8; ++i) {
                acc[i][0] = fma2(a2[i], b0, acc[i][0]);
                acc[i][1] = fma2(a2[i], b1, acc[i][1]);
                acc[i][2] = fma2(a2[i], b2, acc[i][2]);
                acc[i][3] = fma2(a2[i], b3, acc[i][3]);
            }
        }
        __syncthreads();
    }

    // Epilogue: unpack pairs, vectorized fp32 stores.
    #pragma unroll
    for (int i = 0; i < 8; ++i) {
        float2 c0 = unpack2(acc[i][0]);
        float2 c1 = unpack2(acc[i][1]);
        float2 c2 = unpack2(acc[i][2]);
        float2 c3 = unpack2(acc[i][3]);
        size_t off = (size_t)(m0 + ty * 8 + i) * N + n0 + tx * 8;
        *(float4*)(C + off)     = make_float4(c0.x, c0.y, c1.x, c1.y);
        *(float4*)(C + off + 4) = make_float4(c2.x, c2.y, c3.x, c3.y);
    }
}

// ---------------------------------------------------------------------------
// Row softmax in place: one 256-thread block per row of length n (=2048).
// ---------------------------------------------------------------------------
__global__ void softmax_rows(float* __restrict__ S, int n)
{
    __shared__ float red[256];
    float* p = S + (size_t)blockIdx.x * n;
    const int tid = threadIdx.x;

    float lmax = -3.402823466e38f;
    for (int i = tid; i < n; i += 256) lmax = fmaxf(lmax, p[i]);
    red[tid] = lmax; __syncthreads();
    #pragma unroll
    for (int s = 128; s > 0; s >>= 1) {
        if (tid < s) red[tid] = fmaxf(red[tid], red[tid + s]);
        __syncthreads();
    }
    const float m = red[0];
    __syncthreads();

    float lsum = 0.f;
    for (int i = tid; i < n; i += 256) {
        float e = __expf(p[i] - m);
        p[i] = e;
        lsum += e;
    }
    red[tid] = lsum; __syncthreads();
    #pragma unroll
    for (int s = 128; s > 0; s >>= 1) {
        if (tid < s) red[tid] += red[tid + s];
        __syncthreads();
    }
    const float inv = 1.0f / red[0];
    for (int i = tid; i < n; i += 256) p[i] *= inv;
}

// ---------------------------------------------------------------------------
// Launch: 3 projection GEMMs -> batched NT GEMM -> softmax -> batched NN GEMM.
// All default-stream kernel launches; graph-capturable; no allocations.
// ---------------------------------------------------------------------------
extern "C" void kernel_launch(void* const* d_in, const int* in_sizes, int n_in,
                              void* d_out, int out_size)
{
    const float* X  = (const float*)d_in[0];   // [B,S,D]  = [8192,1024] flat
    const float* Wq = (const float*)d_in[1];   // [D,U]
    const float* Wk = (const float*)d_in[2];
    const float* Wv = (const float*)d_in[3];
    float* out = (float*)d_out;                // [B,S,U]

    float *qp, *kp, *vp, *sp;
    cudaGetSymbolAddress((void**)&qp, g_q);
    cudaGetSymbolAddress((void**)&kp, g_k);
    cudaGetSymbolAddress((void**)&vp, g_v);
    cudaGetSymbolAddress((void**)&sp, g_s);

    const dim3 blk(256);
    const long long sQKV = (long long)SSQ * UU;   // per-batch Q/K/V stride
    const long long sSC  = (long long)SSQ * SSQ;  // per-batch scores stride

    // 1) Projections: [8192,1024] @ [1024,1024] (batch dim folded into M).
    {
        dim3 grid(UU / 128, (BB * SSQ) / 128, 1);
        gemm128x128<false><<<grid, blk>>>(X, Wq, qp, BB * SSQ, UU, DD, 0, 0, 0);
        gemm128x128<false><<<grid, blk>>>(X, Wk, kp, BB * SSQ, UU, DD, 0, 0, 0);
        gemm128x128<false><<<grid, blk>>>(X, Wv, vp, BB * SSQ, UU, DD, 0, 0, 0);
    }

    // 2) scores[b] = Q[b] @ K[b]^T : [2048,2048], K-dim = 1024.
    {
        dim3 grid(SSQ / 128, SSQ / 128, BB);
        gemm128x128<true><<<grid, blk>>>(qp, kp, sp, SSQ, SSQ, UU,
                                         sQKV, sQKV, sSC);
    }

    // 3) Row softmax over all B*S rows of length S.
    softmax_rows<<<BB * SSQ, 256>>>(sp, SSQ);

    // 4) out[b] = P[b] @ V[b] : [2048,1024], K-dim = 2048.
    {
        dim3 grid(UU / 128, SSQ / 128, BB);
        gemm128x128<false><<<grid, blk>>>(sp, vp, out, SSQ, UU, SSQ,
                                          sSC, sQKV, sQKV);
    }
}